// round 10
// baseline (speedup 1.0000x reference)
#include <cuda_runtime.h>
#include <cuda_fp16.h>
#include <cuda_bf16.h>

// GNN_26242250178821: 2-layer GCN forward, CSR-gather + fp16 feature rows.
// R10: (a) duplicate agg1 launch as a timing probe (idempotent), (b) GEMM
// restructured for issue efficiency (float4 xs broadcast + paired-column W).
//
// RULE: never pass a __device__ symbol as a kernel argument from host code —
// on GB300/ATS the host-shadow address is silently writable.

#define D 64
#define MAXN 150016
#define MAXE  3000064
#define MAXELEM (150016 * 64)

__device__ int    g_deg[MAXN];
__device__ int    g_off[MAXN + 1];
__device__ int    g_pos[MAXN];
__device__ float  g_dinv[MAXN];
__device__ unsigned long long g_edge[MAXE];  // (coef bits << 32) | src
__device__ __half g_xwh[MAXELEM];            // xw rows in fp16 (128 B/row)
__device__ int    g_idx64;                   // 1 if edge_index is int64

__global__ void k_detect(const unsigned long long* __restrict__ p, int nwords) {
    __shared__ int any;
    if (threadIdx.x == 0) any = 0;
    __syncthreads();
    for (int i = threadIdx.x; i < nwords; i += blockDim.x)
        if ((p[i] >> 32) != 0ull) any = 1;
    __syncthreads();
    if (threadIdx.x == 0) g_idx64 = any ? 0 : 1;
}

__device__ __forceinline__ int load_idx(const void* ei, long long i) {
    if (g_idx64) return (int)((const long long*)ei)[i];
    return ((const int*)ei)[i];
}

__global__ void k_zero_deg(int n) {
    int i = blockIdx.x * blockDim.x + threadIdx.x;
    if (i < n) g_deg[i] = 0;
}

__global__ void k_count_deg(const void* __restrict__ ei, int e, int n) {
    int i = blockIdx.x * blockDim.x + threadIdx.x;
    if (i < e) {
        int c = load_idx(ei, (long long)e + i);   // col half
        if ((unsigned)c < (unsigned)n) atomicAdd(&g_deg[c], 1);
    }
}

__global__ void k_dinv(int n) {
    int i = blockIdx.x * blockDim.x + threadIdx.x;
    if (i < n) g_dinv[i] = rsqrtf((float)g_deg[i] + 1.0f);
}

// Single-block (1024 threads) exclusive scan of g_deg into g_off and g_pos.
__global__ void k_scan(int n) {
    __shared__ int warp_sums[32];
    int tid = threadIdx.x;
    int chunk = (n + 1023) / 1024;
    int start = tid * chunk;
    int end = start + chunk; if (end > n) end = n;
    int s = 0;
    for (int i = start; i < end; i++) s += g_deg[i];

    int lane = tid & 31, wid = tid >> 5;
    int v = s;
    #pragma unroll
    for (int o = 1; o < 32; o <<= 1) {
        int t = __shfl_up_sync(~0u, v, o);
        if (lane >= o) v += t;
    }
    if (lane == 31) warp_sums[wid] = v;
    __syncthreads();
    if (wid == 0) {
        int w = warp_sums[lane];
        #pragma unroll
        for (int o = 1; o < 32; o <<= 1) {
            int t = __shfl_up_sync(~0u, w, o);
            if (lane >= o) w += t;
        }
        warp_sums[lane] = w;
    }
    __syncthreads();
    int excl = v - s + (wid > 0 ? warp_sums[wid - 1] : 0);

    int run = excl;
    for (int i = start; i < end; i++) {
        g_off[i] = run;
        g_pos[i] = run;
        run += g_deg[i];
    }
    if (tid == 1023) g_off[n] = run;
}

__global__ void k_build(const void* __restrict__ ei, int e, int n) {
    int i = blockIdx.x * blockDim.x + threadIdx.x;
    if (i < e) {
        int r = load_idx(ei, i);
        int c = load_idx(ei, (long long)e + i);
        if ((unsigned)r < (unsigned)n && (unsigned)c < (unsigned)n) {
            int p = atomicAdd(&g_pos[c], 1);
            float cf = g_dinv[r] * g_dinv[c];
            g_edge[p] = ((unsigned long long)__float_as_uint(cf) << 32)
                        | (unsigned)r;
        }
    }
}

__global__ void k_concat(const float4* __restrict__ u, const float4* __restrict__ it,
                         float4* __restrict__ out0, int nu4, int tot4) {
    int i = blockIdx.x * blockDim.x + threadIdx.x;
    if (i < tot4) out0[i] = (i < nu4) ? u[i] : it[i - nu4];
}

// Register-tiled GEMM: g_xwh[n,64] = fp16( relu?(x)[n,64] @ W[64,64] ).
// Block: 256 threads, 128 rows. Warp w -> rows [16w,16w+16); lane -> cols
// {2*lane, 2*lane+1}. Per 4-k chunk: 4 LDS.64 (W pairs) + 16 LDS.128
// (xs broadcast) + 128 FMA.
__global__ void __launch_bounds__(256) k_gemm64(
        const float* __restrict__ x, const float* __restrict__ W,
        int n, int relu_in) {
    __shared__ float Ws[64 * 64];
    __shared__ float xs[128 * 64];
    int tid = threadIdx.x;
    int row0 = blockIdx.x * 128;
    int nr = n - row0; if (nr > 128) nr = 128;

    for (int i = tid; i < 4096; i += 256) Ws[i] = W[i];
    {
        const float4* x4 = (const float4*)(x + (size_t)row0 * 64);
        float4* xs4w = (float4*)xs;
        int tot4 = nr * 16;
        for (int i = tid; i < tot4; i += 256) {
            float4 v = x4[i];
            if (relu_in) {
                v.x = fmaxf(v.x, 0.0f); v.y = fmaxf(v.y, 0.0f);
                v.z = fmaxf(v.z, 0.0f); v.w = fmaxf(v.w, 0.0f);
            }
            xs4w[i] = v;
        }
        for (int i = nr * 16 + tid; i < 128 * 16; i += 256)
            xs4w[i] = make_float4(0.f, 0.f, 0.f, 0.f);
    }
    __syncthreads();

    int warp = tid >> 5, lane = tid & 31;
    int rbase = warp * 16;
    const float4* xs4 = (const float4*)xs;   // [128][16]
    const float2* Ws2 = (const float2*)Ws;   // [64][32]

    float acc0[16], acc1[16];
    #pragma unroll
    for (int r = 0; r < 16; r++) { acc0[r] = 0.0f; acc1[r] = 0.0f; }

    #pragma unroll 4
    for (int k0 = 0; k0 < 16; k0++) {        // 16 chunks of 4 k-steps
        float2 w0 = Ws2[(k0 * 4 + 0) * 32 + lane];
        float2 w1 = Ws2[(k0 * 4 + 1) * 32 + lane];
        float2 w2 = Ws2[(k0 * 4 + 2) * 32 + lane];
        float2 w3 = Ws2[(k0 * 4 + 3) * 32 + lane];
        #pragma unroll
        for (int r = 0; r < 16; r++) {
            float4 xv = xs4[(rbase + r) * 16 + k0];   // warp broadcast
            acc0[r] = fmaf(xv.x, w0.x, acc0[r]);
            acc1[r] = fmaf(xv.x, w0.y, acc1[r]);
            acc0[r] = fmaf(xv.y, w1.x, acc0[r]);
            acc1[r] = fmaf(xv.y, w1.y, acc1[r]);
            acc0[r] = fmaf(xv.z, w2.x, acc0[r]);
            acc1[r] = fmaf(xv.z, w2.y, acc1[r]);
            acc0[r] = fmaf(xv.w, w3.x, acc0[r]);
            acc1[r] = fmaf(xv.w, w3.y, acc1[r]);
        }
    }

    __half2* xwh2 = (__half2*)g_xwh;
    #pragma unroll
    for (int r = 0; r < 16; r++) {
        int row = rbase + r;
        if (row < nr)
            xwh2[(size_t)(row0 + row) * 32 + lane] =
                __floats2half2_rn(acc0[r], acc1[r]);
    }
}

// Warp per node; lane owns dims {2*lane, 2*lane+1} -> one coalesced 128B row
// load per edge. Batches of 8 independent gathers (MLP=8).
__global__ void k_agg(const float* __restrict__ b, float* __restrict__ out, int n) {
    int node = (blockIdx.x * blockDim.x + threadIdx.x) >> 5;
    int lane = threadIdx.x & 31;
    if (node >= n) return;

    int p0 = g_off[node];
    int p1 = g_off[node + 1];
    float acc0 = 0.0f, acc1 = 0.0f;

    const __half2* xw2 = (const __half2*)g_xwh;

    int p = p0;
    while (p < p1) {
        int cnt = p1 - p; if (cnt > 32) cnt = 32;
        unsigned long long meta = 0;
        if (p + lane < p1) meta = __ldg(&g_edge[p + lane]);

        int j = 0;
        for (; j + 8 <= cnt; j += 8) {
            __half2 h[8]; float cf[8];
            #pragma unroll
            for (int t = 0; t < 8; t++) {
                unsigned long long m = __shfl_sync(~0u, meta, j + t);
                int r = (int)(unsigned)m;
                cf[t] = __uint_as_float((unsigned)(m >> 32));
                h[t] = __ldg(&xw2[(size_t)r * 32 + lane]);
            }
            #pragma unroll
            for (int t = 0; t < 8; t++) {
                float2 f = __half22float2(h[t]);
                acc0 += f.x * cf[t];
                acc1 += f.y * cf[t];
            }
        }
        for (; j < cnt; j++) {
            unsigned long long m = __shfl_sync(~0u, meta, j);
            int r = (int)(unsigned)m;
            float cf = __uint_as_float((unsigned)(m >> 32));
            float2 f = __half22float2(__ldg(&xw2[(size_t)r * 32 + lane]));
            acc0 += f.x * cf;
            acc1 += f.y * cf;
        }
        p += cnt;
    }

    float di = g_dinv[node];
    float d2 = di * di;
    float2 fs = __half22float2(xw2[(size_t)node * 32 + lane]);
    float2 bb = ((const float2*)b)[lane];
    float2 o;
    o.x = acc0 + fs.x * d2 + bb.x;
    o.y = acc1 + fs.y * d2 + bb.y;
    ((float2*)out)[(size_t)node * 32 + lane] = o;
}

extern "C" void kernel_launch(void* const* d_in, const int* in_sizes, int n_in,
                              void* d_out, int out_size) {
    const float* emb_users = (const float*)d_in[0];
    const float* emb_items = (const float*)d_in[1];
    const float* W1 = (const float*)d_in[2];
    const float* b1 = (const float*)d_in[3];
    const float* W2 = (const float*)d_in[4];
    const float* b2 = (const float*)d_in[5];
    const void*  ei = d_in[6];

    int NU = in_sizes[0] / D;
    int NI = in_sizes[1] / D;
    int N  = NU + NI;
    int E  = in_sizes[6] / 2;

    float* out0 = (float*)d_out;
    float* out1 = out0 + (size_t)N * D;
    float* out2 = out1 + (size_t)N * D;

    const int T = 256;
    int gN = (N + T - 1) / T;
    int gE = (E + T - 1) / T;
    int gW = (int)(((long long)N * 32 + T - 1) / T);   // warp per node

    // Position-4 launch = k_gemm64 (ncu capture target).
    k_detect<<<1, 256>>>((const unsigned long long*)ei, 256);
    k_zero_deg<<<gN, T>>>(N);

    int nu4 = NU * (D / 4), tot4 = N * (D / 4);
    k_concat<<<(tot4 + T - 1) / T, T>>>((const float4*)emb_users,
                                        (const float4*)emb_items,
                                        (float4*)out0, nu4, tot4);

    k_gemm64<<<(N + 127) / 128, T>>>(out0, W1, N, 0);   // capture target

    k_count_deg<<<gE, T>>>(ei, E, N);
    k_dinv<<<gN, T>>>(N);
    k_scan<<<1, 1024>>>(N);
    k_build<<<gE, T>>>(ei, E, N);

    // layer 1 aggregation — launched TWICE (idempotent) as a timing probe:
    // dur_R10 - dur_R9 ~= cost of one k_agg.
    k_agg<<<gW, T>>>(b1, out1, N);
    k_agg<<<gW, T>>>(b1, out1, N);

    // layer 2 (relu applied on read of out1)
    k_gemm64<<<(N + 127) / 128, T>>>(out1, W2, N, 1);
    k_agg<<<gW, T>>>(b2, out2, N);
}

// round 11
// speedup vs baseline: 1.9106x; 1.9106x over previous
#include <cuda_runtime.h>
#include <cuda_fp16.h>
#include <cuda_bf16.h>

// GNN_26242250178821: 2-layer GCN forward, CSR-gather + fp16 feature rows.
// R11: multi-block coalesced scan (kills the single-block scan hotspot),
// concat fused into gemm1, dinv fused into scan, vectorized edge loads.
//
// RULE: never pass a __device__ symbol as a kernel argument from host code —
// on GB300/ATS the host-shadow address is silently writable.

#define D 64
#define MAXN 150016
#define MAXE  3000064
#define MAXELEM (150016 * 64)
#define MAXB 1024          // max scan blocks (N/256 = 586)

__device__ int    g_deg[MAXN];
__device__ int    g_off[MAXN + 1];
__device__ int    g_pos[MAXN];
__device__ float  g_dinv[MAXN];
__device__ int    g_bsum[MAXB];
__device__ int    g_bpre[MAXB];
__device__ unsigned long long g_edge[MAXE];  // (coef bits << 32) | src
__device__ __half g_xwh[MAXELEM];            // xw rows in fp16 (128 B/row)
__device__ int    g_idx64;                   // 1 if edge_index is int64

__global__ void k_detect(const unsigned long long* __restrict__ p, int nwords) {
    __shared__ int any;
    if (threadIdx.x == 0) any = 0;
    __syncthreads();
    for (int i = threadIdx.x; i < nwords; i += blockDim.x)
        if ((p[i] >> 32) != 0ull) any = 1;
    __syncthreads();
    if (threadIdx.x == 0) g_idx64 = any ? 0 : 1;
}

__global__ void k_zero_deg(int n) {
    int i = blockIdx.x * blockDim.x + threadIdx.x;
    if (i < n) g_deg[i] = 0;
}

// 2 edges per thread, vectorized col loads.
__global__ void k_count_deg(const void* __restrict__ ei, int e, int n) {
    int i = (blockIdx.x * blockDim.x + threadIdx.x) * 2;
    if (i >= e) return;
    int c0, c1 = -1;
    if (i + 1 < e) {
        if (g_idx64) {
            longlong2 v = *(const longlong2*)((const long long*)ei + (size_t)e + i);
            c0 = (int)v.x; c1 = (int)v.y;
        } else {
            int2 v = *(const int2*)((const int*)ei + (size_t)e + i);
            c0 = v.x; c1 = v.y;
        }
    } else {
        c0 = g_idx64 ? (int)((const long long*)ei)[(size_t)e + i]
                     : ((const int*)ei)[(size_t)e + i];
    }
    if ((unsigned)c0 < (unsigned)n) atomicAdd(&g_deg[c0], 1);
    if (c1 >= 0 && (unsigned)c1 < (unsigned)n) atomicAdd(&g_deg[c1], 1);
}

// Scan phase 1: coalesced per-block sums of g_deg (256 elems/block).
__global__ void k_scan_bsum(int n) {
    __shared__ int wsum[8];
    int tid = threadIdx.x, lane = tid & 31, wid = tid >> 5;
    int i = blockIdx.x * 256 + tid;
    int d = (i < n) ? g_deg[i] : 0;
    int v = d;
    #pragma unroll
    for (int o = 16; o > 0; o >>= 1) v += __shfl_down_sync(~0u, v, o);
    if (lane == 0) wsum[wid] = v;
    __syncthreads();
    if (tid == 0) {
        int s = 0;
        #pragma unroll
        for (int w = 0; w < 8; w++) s += wsum[w];
        g_bsum[blockIdx.x] = s;
    }
}

// Scan phase 2: single block exclusive scan of nb block sums (nb <= 1024).
__global__ void k_scan_bpre(int nb) {
    __shared__ int wsum[32];
    int tid = threadIdx.x, lane = tid & 31, wid = tid >> 5;
    int d = (tid < nb) ? g_bsum[tid] : 0;
    int v = d;
    #pragma unroll
    for (int o = 1; o < 32; o <<= 1) {
        int t = __shfl_up_sync(~0u, v, o);
        if (lane >= o) v += t;
    }
    if (lane == 31) wsum[wid] = v;
    __syncthreads();
    if (wid == 0) {
        int w = wsum[lane];
        #pragma unroll
        for (int o = 1; o < 32; o <<= 1) {
            int t = __shfl_up_sync(~0u, w, o);
            if (lane >= o) w += t;
        }
        wsum[lane] = w;
    }
    __syncthreads();
    int excl = v - d + (wid > 0 ? wsum[wid - 1] : 0);
    if (tid < nb) g_bpre[tid] = excl;
}

// Scan phase 3: coalesced per-element exclusive offsets + dinv.
__global__ void k_scan_write(int n) {
    __shared__ int wsum[8];
    int tid = threadIdx.x, lane = tid & 31, wid = tid >> 5;
    int i = blockIdx.x * 256 + tid;
    int d = (i < n) ? g_deg[i] : 0;
    int v = d;
    #pragma unroll
    for (int o = 1; o < 32; o <<= 1) {
        int t = __shfl_up_sync(~0u, v, o);
        if (lane >= o) v += t;
    }
    if (lane == 31) wsum[wid] = v;
    __syncthreads();
    if (wid == 0 && lane < 8) {
        int w = wsum[lane];
        #pragma unroll
        for (int o = 1; o < 8; o <<= 1) {
            int t = __shfl_up_sync(0xFFu, w, o);
            if (lane >= o) w += t;
        }
        wsum[lane] = w;
    }
    __syncthreads();
    int excl = v - d + (wid > 0 ? wsum[wid - 1] : 0) + g_bpre[blockIdx.x];
    if (i < n) {
        g_off[i] = excl;
        g_pos[i] = excl;
        g_dinv[i] = rsqrtf((float)d + 1.0f);
        if (i == n - 1) g_off[n] = excl + d;
    }
}

// 2 edges per thread, vectorized row/col loads; scattered 8B store per edge.
__global__ void k_build(const void* __restrict__ ei, int e, int n) {
    int i = (blockIdx.x * blockDim.x + threadIdx.x) * 2;
    if (i >= e) return;
    int r0, c0, r1 = -1, c1 = -1;
    if (i + 1 < e) {
        if (g_idx64) {
            longlong2 rv = *(const longlong2*)((const long long*)ei + i);
            longlong2 cv = *(const longlong2*)((const long long*)ei + (size_t)e + i);
            r0 = (int)rv.x; r1 = (int)rv.y; c0 = (int)cv.x; c1 = (int)cv.y;
        } else {
            int2 rv = *(const int2*)((const int*)ei + i);
            int2 cv = *(const int2*)((const int*)ei + (size_t)e + i);
            r0 = rv.x; r1 = rv.y; c0 = cv.x; c1 = cv.y;
        }
    } else {
        if (g_idx64) {
            r0 = (int)((const long long*)ei)[i];
            c0 = (int)((const long long*)ei)[(size_t)e + i];
        } else {
            r0 = ((const int*)ei)[i];
            c0 = ((const int*)ei)[(size_t)e + i];
        }
    }
    if ((unsigned)r0 < (unsigned)n && (unsigned)c0 < (unsigned)n) {
        int p = atomicAdd(&g_pos[c0], 1);
        float cf = g_dinv[r0] * g_dinv[c0];
        g_edge[p] = ((unsigned long long)__float_as_uint(cf) << 32) | (unsigned)r0;
    }
    if (r1 >= 0 && (unsigned)r1 < (unsigned)n && (unsigned)c1 < (unsigned)n) {
        int p = atomicAdd(&g_pos[c1], 1);
        float cf = g_dinv[r1] * g_dinv[c1];
        g_edge[p] = ((unsigned long long)__float_as_uint(cf) << 32) | (unsigned)r1;
    }
}

// Layer-1 GEMM fused with concat: reads users/items directly, writes out0
// AND g_xwh. Block: 256 threads, 128 rows; warp w -> rows [16w,16w+16);
// lane -> cols {2*lane, 2*lane+1}.
__global__ void __launch_bounds__(256) k_gemm_l1(
        const float4* __restrict__ u, const float4* __restrict__ it,
        const float* __restrict__ W, float4* __restrict__ out0,
        int nu4, int n) {
    __shared__ float Ws[64 * 64];
    __shared__ float xs[128 * 64];
    int tid = threadIdx.x;
    int row0 = blockIdx.x * 128;
    int nr = n - row0; if (nr > 128) nr = 128;

    for (int i = tid; i < 4096; i += 256) Ws[i] = W[i];
    {
        float4* xs4w = (float4*)xs;
        int tot4 = nr * 16;
        int g0 = row0 * 16;
        for (int i = tid; i < tot4; i += 256) {
            int gi = g0 + i;
            float4 v = (gi < nu4) ? u[gi] : it[gi - nu4];
            xs4w[i] = v;
            out0[gi] = v;               // fused concat output
        }
        for (int i = nr * 16 + tid; i < 128 * 16; i += 256)
            xs4w[i] = make_float4(0.f, 0.f, 0.f, 0.f);
    }
    __syncthreads();

    int warp = tid >> 5, lane = tid & 31;
    int rbase = warp * 16;
    const float4* xs4 = (const float4*)xs;
    const float2* Ws2 = (const float2*)Ws;

    float acc0[16], acc1[16];
    #pragma unroll
    for (int r = 0; r < 16; r++) { acc0[r] = 0.0f; acc1[r] = 0.0f; }

    #pragma unroll 4
    for (int k0 = 0; k0 < 16; k0++) {
        float2 w0 = Ws2[(k0 * 4 + 0) * 32 + lane];
        float2 w1 = Ws2[(k0 * 4 + 1) * 32 + lane];
        float2 w2 = Ws2[(k0 * 4 + 2) * 32 + lane];
        float2 w3 = Ws2[(k0 * 4 + 3) * 32 + lane];
        #pragma unroll
        for (int r = 0; r < 16; r++) {
            float4 xv = xs4[(rbase + r) * 16 + k0];
            acc0[r] = fmaf(xv.x, w0.x, acc0[r]);
            acc1[r] = fmaf(xv.x, w0.y, acc1[r]);
            acc0[r] = fmaf(xv.y, w1.x, acc0[r]);
            acc1[r] = fmaf(xv.y, w1.y, acc1[r]);
            acc0[r] = fmaf(xv.z, w2.x, acc0[r]);
            acc1[r] = fmaf(xv.z, w2.y, acc1[r]);
            acc0[r] = fmaf(xv.w, w3.x, acc0[r]);
            acc1[r] = fmaf(xv.w, w3.y, acc1[r]);
        }
    }

    __half2* xwh2 = (__half2*)g_xwh;
    #pragma unroll
    for (int r = 0; r < 16; r++) {
        int row = rbase + r;
        if (row < nr)
            xwh2[(size_t)(row0 + row) * 32 + lane] =
                __floats2half2_rn(acc0[r], acc1[r]);
    }
}

// Layer-2 GEMM: reads out1 with relu.
__global__ void __launch_bounds__(256) k_gemm_l2(
        const float* __restrict__ x, const float* __restrict__ W, int n) {
    __shared__ float Ws[64 * 64];
    __shared__ float xs[128 * 64];
    int tid = threadIdx.x;
    int row0 = blockIdx.x * 128;
    int nr = n - row0; if (nr > 128) nr = 128;

    for (int i = tid; i < 4096; i += 256) Ws[i] = W[i];
    {
        const float4* x4 = (const float4*)(x + (size_t)row0 * 64);
        float4* xs4w = (float4*)xs;
        int tot4 = nr * 16;
        for (int i = tid; i < tot4; i += 256) {
            float4 v = x4[i];
            v.x = fmaxf(v.x, 0.0f); v.y = fmaxf(v.y, 0.0f);
            v.z = fmaxf(v.z, 0.0f); v.w = fmaxf(v.w, 0.0f);
            xs4w[i] = v;
        }
        for (int i = nr * 16 + tid; i < 128 * 16; i += 256)
            xs4w[i] = make_float4(0.f, 0.f, 0.f, 0.f);
    }
    __syncthreads();

    int warp = tid >> 5, lane = tid & 31;
    int rbase = warp * 16;
    const float4* xs4 = (const float4*)xs;
    const float2* Ws2 = (const float2*)Ws;

    float acc0[16], acc1[16];
    #pragma unroll
    for (int r = 0; r < 16; r++) { acc0[r] = 0.0f; acc1[r] = 0.0f; }

    #pragma unroll 4
    for (int k0 = 0; k0 < 16; k0++) {
        float2 w0 = Ws2[(k0 * 4 + 0) * 32 + lane];
        float2 w1 = Ws2[(k0 * 4 + 1) * 32 + lane];
        float2 w2 = Ws2[(k0 * 4 + 2) * 32 + lane];
        float2 w3 = Ws2[(k0 * 4 + 3) * 32 + lane];
        #pragma unroll
        for (int r = 0; r < 16; r++) {
            float4 xv = xs4[(rbase + r) * 16 + k0];
            acc0[r] = fmaf(xv.x, w0.x, acc0[r]);
            acc1[r] = fmaf(xv.x, w0.y, acc1[r]);
            acc0[r] = fmaf(xv.y, w1.x, acc0[r]);
            acc1[r] = fmaf(xv.y, w1.y, acc1[r]);
            acc0[r] = fmaf(xv.z, w2.x, acc0[r]);
            acc1[r] = fmaf(xv.z, w2.y, acc1[r]);
            acc0[r] = fmaf(xv.w, w3.x, acc0[r]);
            acc1[r] = fmaf(xv.w, w3.y, acc1[r]);
        }
    }

    __half2* xwh2 = (__half2*)g_xwh;
    #pragma unroll
    for (int r = 0; r < 16; r++) {
        int row = rbase + r;
        if (row < nr)
            xwh2[(size_t)(row0 + row) * 32 + lane] =
                __floats2half2_rn(acc0[r], acc1[r]);
    }
}

// Warp per node; lane owns dims {2*lane, 2*lane+1}; batches of 8 gathers.
__global__ void k_agg(const float* __restrict__ b, float* __restrict__ out, int n) {
    int node = (blockIdx.x * blockDim.x + threadIdx.x) >> 5;
    int lane = threadIdx.x & 31;
    if (node >= n) return;

    int p0 = g_off[node];
    int p1 = g_off[node + 1];
    float acc0 = 0.0f, acc1 = 0.0f;

    const __half2* xw2 = (const __half2*)g_xwh;

    int p = p0;
    while (p < p1) {
        int cnt = p1 - p; if (cnt > 32) cnt = 32;
        unsigned long long meta = 0;
        if (p + lane < p1) meta = __ldg(&g_edge[p + lane]);

        int j = 0;
        for (; j + 8 <= cnt; j += 8) {
            __half2 h[8]; float cf[8];
            #pragma unroll
            for (int t = 0; t < 8; t++) {
                unsigned long long m = __shfl_sync(~0u, meta, j + t);
                int r = (int)(unsigned)m;
                cf[t] = __uint_as_float((unsigned)(m >> 32));
                h[t] = __ldg(&xw2[(size_t)r * 32 + lane]);
            }
            #pragma unroll
            for (int t = 0; t < 8; t++) {
                float2 f = __half22float2(h[t]);
                acc0 += f.x * cf[t];
                acc1 += f.y * cf[t];
            }
        }
        for (; j < cnt; j++) {
            unsigned long long m = __shfl_sync(~0u, meta, j);
            int r = (int)(unsigned)m;
            float cf = __uint_as_float((unsigned)(m >> 32));
            float2 f = __half22float2(__ldg(&xw2[(size_t)r * 32 + lane]));
            acc0 += f.x * cf;
            acc1 += f.y * cf;
        }
        p += cnt;
    }

    float di = g_dinv[node];
    float d2 = di * di;
    float2 fs = __half22float2(xw2[(size_t)node * 32 + lane]);
    float2 bb = ((const float2*)b)[lane];
    float2 o;
    o.x = acc0 + fs.x * d2 + bb.x;
    o.y = acc1 + fs.y * d2 + bb.y;
    ((float2*)out)[(size_t)node * 32 + lane] = o;
}

extern "C" void kernel_launch(void* const* d_in, const int* in_sizes, int n_in,
                              void* d_out, int out_size) {
    const float* emb_users = (const float*)d_in[0];
    const float* emb_items = (const float*)d_in[1];
    const float* W1 = (const float*)d_in[2];
    const float* b1 = (const float*)d_in[3];
    const float* W2 = (const float*)d_in[4];
    const float* b2 = (const float*)d_in[5];
    const void*  ei = d_in[6];

    int NU = in_sizes[0] / D;
    int NI = in_sizes[1] / D;
    int N  = NU + NI;
    int E  = in_sizes[6] / 2;

    float* out0 = (float*)d_out;
    float* out1 = out0 + (size_t)N * D;
    float* out2 = out1 + (size_t)N * D;

    const int T = 256;
    int gN  = (N + T - 1) / T;           // also #scan blocks
    int gE2 = (E / 2 + T - 1) / T;       // 2 edges per thread
    int gW  = (int)(((long long)N * 32 + T - 1) / T);

    // Launch order: slot #4 (ncu capture) = k_count_deg.
    k_detect<<<1, 256>>>((const unsigned long long*)ei, 256);       // 1
    k_zero_deg<<<gN, T>>>(N);                                        // 2
    k_gemm_l1<<<(N + 127) / 128, T>>>((const float4*)emb_users,      // 3
                                      (const float4*)emb_items,
                                      W1, (float4*)out0, NU * 16, N);
    k_count_deg<<<gE2, T>>>(ei, E, N);                               // 4 (capture)
    k_scan_bsum<<<gN, T>>>(N);                                       // 5
    k_scan_bpre<<<1, 1024>>>(gN);                                    // 6
    k_scan_write<<<gN, T>>>(N);                                      // 7
    k_build<<<gE2, T>>>(ei, E, N);                                   // 8
    k_agg<<<gW, T>>>(b1, out1, N);                                   // 9
    k_gemm_l2<<<(N + 127) / 128, T>>>(out1, W2, N);                  // 10
    k_agg<<<gW, T>>>(b2, out2, N);                                   // 11
}

// round 12
// speedup vs baseline: 2.4192x; 1.2662x over previous
#include <cuda_runtime.h>
#include <cuda_fp16.h>
#include <cuda_bf16.h>
#include <cstdint>

// GNN_26242250178821: 2-layer GCN forward, CSR-gather + fp16 feature rows.
// R12: tensor-core GEMM (mma.sync m16n8k16 fp16->fp32), count_deg grid-fused
// into the layer-1 GEMM launch, detect+zero fused.
//
// RULE: never pass a __device__ symbol as a kernel argument from host code —
// on GB300/ATS the host-shadow address is silently writable.

#define D 64
#define MAXN 150016
#define MAXE  3000064
#define MAXELEM (150016 * 64)
#define MAXB 1024

__device__ int    g_deg[MAXN];
__device__ int    g_off[MAXN + 1];
__device__ int    g_pos[MAXN];
__device__ float  g_dinv[MAXN];
__device__ int    g_bsum[MAXB];
__device__ int    g_bpre[MAXB];
__device__ unsigned long long g_edge[MAXE];  // (coef bits << 32) | src
__device__ __half g_xwh[MAXELEM];            // xw rows fp16, 128 B/row
__device__ int    g_idx64;

__device__ __forceinline__ int load_idx(const void* ei, long long i) {
    if (g_idx64) return (int)((const long long*)ei)[i];
    return ((const int*)ei)[i];
}

// blocks [0,gn): zero g_deg; block gn: dtype probe.
__global__ void k_init(const unsigned long long* __restrict__ p, int n, int gn) {
    if (blockIdx.x == (unsigned)gn) {
        __shared__ int any;
        if (threadIdx.x == 0) any = 0;
        __syncthreads();
        for (int i = threadIdx.x; i < 256; i += blockDim.x)
            if ((p[i] >> 32) != 0ull) any = 1;
        __syncthreads();
        if (threadIdx.x == 0) g_idx64 = any ? 0 : 1;
        return;
    }
    int i = blockIdx.x * blockDim.x + threadIdx.x;
    if (i < n) g_deg[i] = 0;
}

// ---------------- tensor-core GEMM core ----------------
// xs: fp16 [128][72] (144B row stride), Ws: fp16 [64][72].
// 8 warps, warp w -> rows [16w,16w+16). Computes 16x64 per warp via
// 4 k-steps x 8 n-tiles of mma.m16n8k16, writes g_xwh rows [row0, row0+nr).

__device__ __forceinline__ void ldsm_x4(uint32_t& r0, uint32_t& r1,
                                        uint32_t& r2, uint32_t& r3, uint32_t a) {
    asm volatile("ldmatrix.sync.aligned.m8n8.x4.shared.b16 {%0,%1,%2,%3},[%4];"
                 : "=r"(r0), "=r"(r1), "=r"(r2), "=r"(r3) : "r"(a));
}
__device__ __forceinline__ void ldsm_x4t(uint32_t& r0, uint32_t& r1,
                                         uint32_t& r2, uint32_t& r3, uint32_t a) {
    asm volatile("ldmatrix.sync.aligned.m8n8.x4.trans.shared.b16 {%0,%1,%2,%3},[%4];"
                 : "=r"(r0), "=r"(r1), "=r"(r2), "=r"(r3) : "r"(a));
}
__device__ __forceinline__ void mma16816(float* d, uint32_t a0, uint32_t a1,
                                         uint32_t a2, uint32_t a3,
                                         uint32_t b0, uint32_t b1) {
    asm volatile(
        "mma.sync.aligned.m16n8k16.row.col.f32.f16.f16.f32 "
        "{%0,%1,%2,%3},{%4,%5,%6,%7},{%8,%9},{%0,%1,%2,%3};"
        : "+f"(d[0]), "+f"(d[1]), "+f"(d[2]), "+f"(d[3])
        : "r"(a0), "r"(a1), "r"(a2), "r"(a3), "r"(b0), "r"(b1));
}

__device__ __forceinline__ void gemm_core(const __half* xs, const __half* Ws,
                                          int row0, int n) {
    int tid = threadIdx.x;
    int warp = tid >> 5, lane = tid & 31;
    int warpRow = warp * 16;

    float d[8][4];
    #pragma unroll
    for (int t = 0; t < 8; t++)
        #pragma unroll
        for (int q = 0; q < 4; q++) d[t][q] = 0.0f;

    int rin = lane & 15, half_sel = lane >> 4;
    #pragma unroll
    for (int ks = 0; ks < 4; ks++) {
        uint32_t a0, a1, a2, a3;
        uint32_t aaddr = (uint32_t)__cvta_generic_to_shared(
            &xs[(warpRow + rin) * 72 + ks * 16 + half_sel * 8]);
        ldsm_x4(a0, a1, a2, a3, aaddr);
        #pragma unroll
        for (int jp = 0; jp < 4; jp++) {
            uint32_t b0, b1, b2, b3;
            uint32_t baddr = (uint32_t)__cvta_generic_to_shared(
                &Ws[(ks * 16 + rin) * 72 + (jp * 2 + half_sel) * 8]);
            ldsm_x4t(b0, b1, b2, b3, baddr);
            mma16816(d[jp * 2],     a0, a1, a2, a3, b0, b1);
            mma16816(d[jp * 2 + 1], a0, a1, a2, a3, b2, b3);
        }
    }

    // Epilogue: D frag rows = groupID / groupID+8, cols = tig*2, tig*2+1.
    int group = lane >> 2, tig = lane & 3;
    int row_lo = row0 + warpRow + group;
    int row_hi = row_lo + 8;
    __half2* xwh2 = (__half2*)g_xwh;
    #pragma unroll
    for (int t = 0; t < 8; t++) {
        int cidx = t * 4 + tig;   // half2 column index (col = t*8 + tig*2)
        if (row_lo < n)
            xwh2[(size_t)row_lo * 32 + cidx] = __floats2half2_rn(d[t][0], d[t][1]);
        if (row_hi < n)
            xwh2[(size_t)row_hi * 32 + cidx] = __floats2half2_rn(d[t][2], d[t][3]);
    }
}

__device__ __forceinline__ void stage_W(const float* __restrict__ W, __half* Ws) {
    const float2* W2 = (const float2*)W;
    for (int i = threadIdx.x; i < 2048; i += 256) {
        int k = i >> 5, np = i & 31;
        float2 w = W2[i];
        *(__half2*)&Ws[k * 72 + np * 2] = __floats2half2_rn(w.x, w.y);
    }
}

// Layer-1 GEMM (fused concat-out0 + count_deg).
// blocks [0, gemmBlocks): GEMM; blocks >= gemmBlocks: degree count.
__global__ void __launch_bounds__(256) k_gemm1_count(
        const float4* __restrict__ u, const float4* __restrict__ it,
        const float* __restrict__ W, float4* __restrict__ out0,
        int nu4, int n, int gemmBlocks, const void* __restrict__ ei, int e) {
    __shared__ __half xs[128 * 72];
    __shared__ __half Ws[64 * 72];

    if (blockIdx.x >= (unsigned)gemmBlocks) {
        int bid = blockIdx.x - gemmBlocks;
        int i = (bid * 256 + threadIdx.x) * 2;
        if (i >= e) return;
        int c0, c1 = -1;
        if (i + 1 < e) {
            if (g_idx64) {
                longlong2 v = *(const longlong2*)((const long long*)ei + (size_t)e + i);
                c0 = (int)v.x; c1 = (int)v.y;
            } else {
                int2 v = *(const int2*)((const int*)ei + (size_t)e + i);
                c0 = v.x; c1 = v.y;
            }
        } else {
            c0 = g_idx64 ? (int)((const long long*)ei)[(size_t)e + i]
                         : ((const int*)ei)[(size_t)e + i];
        }
        if ((unsigned)c0 < (unsigned)n) atomicAdd(&g_deg[c0], 1);
        if (c1 >= 0 && (unsigned)c1 < (unsigned)n) atomicAdd(&g_deg[c1], 1);
        return;
    }

    int tid = threadIdx.x;
    int row0 = blockIdx.x * 128;
    int nr = n - row0; if (nr > 128) nr = 128;

    stage_W(W, Ws);
    {
        int tot4 = nr * 16, g0 = row0 * 16;
        for (int i = tid; i < tot4; i += 256) {
            int gi = g0 + i;
            float4 v = (gi < nu4) ? u[gi] : it[gi - nu4];
            out0[gi] = v;                       // fused concat
            int row = i >> 4, k4 = i & 15;
            __half2* p = (__half2*)&xs[row * 72 + k4 * 4];
            p[0] = __floats2half2_rn(v.x, v.y);
            p[1] = __floats2half2_rn(v.z, v.w);
        }
        for (int i = nr * 16 + tid; i < 128 * 16; i += 256) {
            int row = i >> 4, k4 = i & 15;
            __half2* p = (__half2*)&xs[row * 72 + k4 * 4];
            p[0] = __half2half2(__float2half(0.0f));
            p[1] = __half2half2(__float2half(0.0f));
        }
    }
    __syncthreads();
    gemm_core(xs, Ws, row0, n);
}

// Layer-2 GEMM: reads out1 fp32 with relu.
__global__ void __launch_bounds__(256) k_gemm_l2(
        const float* __restrict__ x, const float* __restrict__ W, int n) {
    __shared__ __half xs[128 * 72];
    __shared__ __half Ws[64 * 72];
    int tid = threadIdx.x;
    int row0 = blockIdx.x * 128;
    int nr = n - row0; if (nr > 128) nr = 128;

    stage_W(W, Ws);
    {
        const float4* x4 = (const float4*)(x + (size_t)row0 * 64);
        int tot4 = nr * 16;
        for (int i = tid; i < tot4; i += 256) {
            float4 v = x4[i];
            v.x = fmaxf(v.x, 0.0f); v.y = fmaxf(v.y, 0.0f);
            v.z = fmaxf(v.z, 0.0f); v.w = fmaxf(v.w, 0.0f);
            int row = i >> 4, k4 = i & 15;
            __half2* p = (__half2*)&xs[row * 72 + k4 * 4];
            p[0] = __floats2half2_rn(v.x, v.y);
            p[1] = __floats2half2_rn(v.z, v.w);
        }
        for (int i = nr * 16 + tid; i < 128 * 16; i += 256) {
            int row = i >> 4, k4 = i & 15;
            __half2* p = (__half2*)&xs[row * 72 + k4 * 4];
            p[0] = __half2half2(__float2half(0.0f));
            p[1] = __half2half2(__float2half(0.0f));
        }
    }
    __syncthreads();
    gemm_core(xs, Ws, row0, n);
}

// ---------------- scan / build / agg (unchanged from R11) ----------------

__global__ void k_scan_bsum(int n) {
    __shared__ int wsum[8];
    int tid = threadIdx.x, lane = tid & 31, wid = tid >> 5;
    int i = blockIdx.x * 256 + tid;
    int d = (i < n) ? g_deg[i] : 0;
    int v = d;
    #pragma unroll
    for (int o = 16; o > 0; o >>= 1) v += __shfl_down_sync(~0u, v, o);
    if (lane == 0) wsum[wid] = v;
    __syncthreads();
    if (tid == 0) {
        int s = 0;
        #pragma unroll
        for (int w = 0; w < 8; w++) s += wsum[w];
        g_bsum[blockIdx.x] = s;
    }
}

__global__ void k_scan_bpre(int nb) {
    __shared__ int wsum[32];
    int tid = threadIdx.x, lane = tid & 31, wid = tid >> 5;
    int d = (tid < nb) ? g_bsum[tid] : 0;
    int v = d;
    #pragma unroll
    for (int o = 1; o < 32; o <<= 1) {
        int t = __shfl_up_sync(~0u, v, o);
        if (lane >= o) v += t;
    }
    if (lane == 31) wsum[wid] = v;
    __syncthreads();
    if (wid == 0) {
        int w = wsum[lane];
        #pragma unroll
        for (int o = 1; o < 32; o <<= 1) {
            int t = __shfl_up_sync(~0u, w, o);
            if (lane >= o) w += t;
        }
        wsum[lane] = w;
    }
    __syncthreads();
    int excl = v - d + (wid > 0 ? wsum[wid - 1] : 0);
    if (tid < nb) g_bpre[tid] = excl;
}

__global__ void k_scan_write(int n) {
    __shared__ int wsum[8];
    int tid = threadIdx.x, lane = tid & 31, wid = tid >> 5;
    int i = blockIdx.x * 256 + tid;
    int d = (i < n) ? g_deg[i] : 0;
    int v = d;
    #pragma unroll
    for (int o = 1; o < 32; o <<= 1) {
        int t = __shfl_up_sync(~0u, v, o);
        if (lane >= o) v += t;
    }
    if (lane == 31) wsum[wid] = v;
    __syncthreads();
    if (wid == 0 && lane < 8) {
        int w = wsum[lane];
        #pragma unroll
        for (int o = 1; o < 8; o <<= 1) {
            int t = __shfl_up_sync(0xFFu, w, o);
            if (lane >= o) w += t;
        }
        wsum[lane] = w;
    }
    __syncthreads();
    int excl = v - d + (wid > 0 ? wsum[wid - 1] : 0) + g_bpre[blockIdx.x];
    if (i < n) {
        g_off[i] = excl;
        g_pos[i] = excl;
        g_dinv[i] = rsqrtf((float)d + 1.0f);
        if (i == n - 1) g_off[n] = excl + d;
    }
}

__global__ void k_build(const void* __restrict__ ei, int e, int n) {
    int i = (blockIdx.x * blockDim.x + threadIdx.x) * 2;
    if (i >= e) return;
    int r0, c0, r1 = -1, c1 = -1;
    if (i + 1 < e) {
        if (g_idx64) {
            longlong2 rv = *(const longlong2*)((const long long*)ei + i);
            longlong2 cv = *(const longlong2*)((const long long*)ei + (size_t)e + i);
            r0 = (int)rv.x; r1 = (int)rv.y; c0 = (int)cv.x; c1 = (int)cv.y;
        } else {
            int2 rv = *(const int2*)((const int*)ei + i);
            int2 cv = *(const int2*)((const int*)ei + (size_t)e + i);
            r0 = rv.x; r1 = rv.y; c0 = cv.x; c1 = cv.y;
        }
    } else {
        if (g_idx64) {
            r0 = (int)((const long long*)ei)[i];
            c0 = (int)((const long long*)ei)[(size_t)e + i];
        } else {
            r0 = ((const int*)ei)[i];
            c0 = ((const int*)ei)[(size_t)e + i];
        }
    }
    if ((unsigned)r0 < (unsigned)n && (unsigned)c0 < (unsigned)n) {
        int p = atomicAdd(&g_pos[c0], 1);
        float cf = g_dinv[r0] * g_dinv[c0];
        g_edge[p] = ((unsigned long long)__float_as_uint(cf) << 32) | (unsigned)r0;
    }
    if (r1 >= 0 && (unsigned)r1 < (unsigned)n && (unsigned)c1 < (unsigned)n) {
        int p = atomicAdd(&g_pos[c1], 1);
        float cf = g_dinv[r1] * g_dinv[c1];
        g_edge[p] = ((unsigned long long)__float_as_uint(cf) << 32) | (unsigned)r1;
    }
}

__global__ void k_agg(const float* __restrict__ b, float* __restrict__ out, int n) {
    int node = (blockIdx.x * blockDim.x + threadIdx.x) >> 5;
    int lane = threadIdx.x & 31;
    if (node >= n) return;

    int p0 = g_off[node];
    int p1 = g_off[node + 1];
    float acc0 = 0.0f, acc1 = 0.0f;

    const __half2* xw2 = (const __half2*)g_xwh;

    int p = p0;
    while (p < p1) {
        int cnt = p1 - p; if (cnt > 32) cnt = 32;
        unsigned long long meta = 0;
        if (p + lane < p1) meta = __ldg(&g_edge[p + lane]);

        int j = 0;
        for (; j + 8 <= cnt; j += 8) {
            __half2 h[8]; float cf[8];
            #pragma unroll
            for (int t = 0; t < 8; t++) {
                unsigned long long m = __shfl_sync(~0u, meta, j + t);
                int r = (int)(unsigned)m;
                cf[t] = __uint_as_float((unsigned)(m >> 32));
                h[t] = __ldg(&xw2[(size_t)r * 32 + lane]);
            }
            #pragma unroll
            for (int t = 0; t < 8; t++) {
                float2 f = __half22float2(h[t]);
                acc0 += f.x * cf[t];
                acc1 += f.y * cf[t];
            }
        }
        for (; j < cnt; j++) {
            unsigned long long m = __shfl_sync(~0u, meta, j);
            int r = (int)(unsigned)m;
            float cf = __uint_as_float((unsigned)(m >> 32));
            float2 f = __half22float2(__ldg(&xw2[(size_t)r * 32 + lane]));
            acc0 += f.x * cf;
            acc1 += f.y * cf;
        }
        p += cnt;
    }

    float di = g_dinv[node];
    float d2 = di * di;
    float2 fs = __half22float2(xw2[(size_t)node * 32 + lane]);
    float2 bb = ((const float2*)b)[lane];
    float2 o;
    o.x = acc0 + fs.x * d2 + bb.x;
    o.y = acc1 + fs.y * d2 + bb.y;
    ((float2*)out)[(size_t)node * 32 + lane] = o;
}

extern "C" void kernel_launch(void* const* d_in, const int* in_sizes, int n_in,
                              void* d_out, int out_size) {
    const float* emb_users = (const float*)d_in[0];
    const float* emb_items = (const float*)d_in[1];
    const float* W1 = (const float*)d_in[2];
    const float* b1 = (const float*)d_in[3];
    const float* W2 = (const float*)d_in[4];
    const float* b2 = (const float*)d_in[5];
    const void*  ei = d_in[6];

    int NU = in_sizes[0] / D;
    int NI = in_sizes[1] / D;
    int N  = NU + NI;
    int E  = in_sizes[6] / 2;

    float* out0 = (float*)d_out;
    float* out1 = out0 + (size_t)N * D;
    float* out2 = out1 + (size_t)N * D;

    const int T = 256;
    int gN  = (N + T - 1) / T;
    int gE2 = (E / 2 + T - 1) / T;
    int gW  = (int)(((long long)N * 32 + T - 1) / T);
    int gG  = (N + 127) / 128;

    k_init<<<gN + 1, T>>>((const unsigned long long*)ei, N, gN);
    k_gemm1_count<<<gG + gE2, T>>>((const float4*)emb_users,
                                   (const float4*)emb_items,
                                   W1, (float4*)out0, NU * 16, N, gG, ei, E);
    k_scan_bsum<<<gN, T>>>(N);
    k_scan_bpre<<<1, 1024>>>(gN);
    k_scan_write<<<gN, T>>>(N);
    k_build<<<gE2, T>>>(ei, E, N);
    k_agg<<<gW, T>>>(b1, out1, N);
    k_gemm_l2<<<gG, T>>>(out1, W2, N);
    k_agg<<<gW, T>>>(b2, out2, N);
}

// round 13
// speedup vs baseline: 2.4560x; 1.0152x over previous
#include <cuda_runtime.h>
#include <cuda_fp16.h>
#include <cuda_bf16.h>
#include <cstdint>

// GNN_26242250178821: 2-layer GCN forward, CSR-gather + fp16 feature rows.
// R13: uniform predicated agg batches (no serial tail), single-kernel scan
// (grid-resident spin sync), 4-edge-per-thread build.
//
// RULE: never pass a __device__ symbol as a kernel argument from host code —
// on GB300/ATS the host-shadow address is silently writable.

#define D 64
#define MAXN 150016
#define MAXE  3000064
#define MAXELEM (150016 * 64)
#define MAXB 1024

__device__ int    g_deg[MAXN];
__device__ int    g_off[MAXN + 1];
__device__ int    g_pos[MAXN];
__device__ float  g_dinv[MAXN];
__device__ int    g_bsum[MAXB];
__device__ int    g_cnt;
__device__ unsigned long long g_edge[MAXE];  // (coef bits << 32) | src
__device__ __half g_xwh[MAXELEM];            // xw rows fp16, 128 B/row
__device__ int    g_idx64;

// blocks [0,gn): zero g_deg; block gn: dtype probe + counter reset.
__global__ void k_init(const unsigned long long* __restrict__ p, int n, int gn) {
    if (blockIdx.x == (unsigned)gn) {
        __shared__ int any;
        if (threadIdx.x == 0) { any = 0; g_cnt = 0; }
        __syncthreads();
        for (int i = threadIdx.x; i < 256; i += blockDim.x)
            if ((p[i] >> 32) != 0ull) any = 1;
        __syncthreads();
        if (threadIdx.x == 0) g_idx64 = any ? 0 : 1;
        return;
    }
    int i = blockIdx.x * blockDim.x + threadIdx.x;
    if (i < n) g_deg[i] = 0;
}

// ---------------- tensor-core GEMM core ----------------

__device__ __forceinline__ void ldsm_x4(uint32_t& r0, uint32_t& r1,
                                        uint32_t& r2, uint32_t& r3, uint32_t a) {
    asm volatile("ldmatrix.sync.aligned.m8n8.x4.shared.b16 {%0,%1,%2,%3},[%4];"
                 : "=r"(r0), "=r"(r1), "=r"(r2), "=r"(r3) : "r"(a));
}
__device__ __forceinline__ void ldsm_x4t(uint32_t& r0, uint32_t& r1,
                                         uint32_t& r2, uint32_t& r3, uint32_t a) {
    asm volatile("ldmatrix.sync.aligned.m8n8.x4.trans.shared.b16 {%0,%1,%2,%3},[%4];"
                 : "=r"(r0), "=r"(r1), "=r"(r2), "=r"(r3) : "r"(a));
}
__device__ __forceinline__ void mma16816(float* d, uint32_t a0, uint32_t a1,
                                         uint32_t a2, uint32_t a3,
                                         uint32_t b0, uint32_t b1) {
    asm volatile(
        "mma.sync.aligned.m16n8k16.row.col.f32.f16.f16.f32 "
        "{%0,%1,%2,%3},{%4,%5,%6,%7},{%8,%9},{%0,%1,%2,%3};"
        : "+f"(d[0]), "+f"(d[1]), "+f"(d[2]), "+f"(d[3])
        : "r"(a0), "r"(a1), "r"(a2), "r"(a3), "r"(b0), "r"(b1));
}

__device__ __forceinline__ void gemm_core(const __half* xs, const __half* Ws,
                                          int row0, int n) {
    int tid = threadIdx.x;
    int warp = tid >> 5, lane = tid & 31;
    int warpRow = warp * 16;

    float d[8][4];
    #pragma unroll
    for (int t = 0; t < 8; t++)
        #pragma unroll
        for (int q = 0; q < 4; q++) d[t][q] = 0.0f;

    int rin = lane & 15, half_sel = lane >> 4;
    #pragma unroll
    for (int ks = 0; ks < 4; ks++) {
        uint32_t a0, a1, a2, a3;
        uint32_t aaddr = (uint32_t)__cvta_generic_to_shared(
            &xs[(warpRow + rin) * 72 + ks * 16 + half_sel * 8]);
        ldsm_x4(a0, a1, a2, a3, aaddr);
        #pragma unroll
        for (int jp = 0; jp < 4; jp++) {
            uint32_t b0, b1, b2, b3;
            uint32_t baddr = (uint32_t)__cvta_generic_to_shared(
                &Ws[(ks * 16 + rin) * 72 + (jp * 2 + half_sel) * 8]);
            ldsm_x4t(b0, b1, b2, b3, baddr);
            mma16816(d[jp * 2],     a0, a1, a2, a3, b0, b1);
            mma16816(d[jp * 2 + 1], a0, a1, a2, a3, b2, b3);
        }
    }

    int group = lane >> 2, tig = lane & 3;
    int row_lo = row0 + warpRow + group;
    int row_hi = row_lo + 8;
    __half2* xwh2 = (__half2*)g_xwh;
    #pragma unroll
    for (int t = 0; t < 8; t++) {
        int cidx = t * 4 + tig;
        if (row_lo < n)
            xwh2[(size_t)row_lo * 32 + cidx] = __floats2half2_rn(d[t][0], d[t][1]);
        if (row_hi < n)
            xwh2[(size_t)row_hi * 32 + cidx] = __floats2half2_rn(d[t][2], d[t][3]);
    }
}

__device__ __forceinline__ void stage_W(const float* __restrict__ W, __half* Ws) {
    const float2* W2 = (const float2*)W;
    for (int i = threadIdx.x; i < 2048; i += 256) {
        int k = i >> 5, np = i & 31;
        float2 w = W2[i];
        *(__half2*)&Ws[k * 72 + np * 2] = __floats2half2_rn(w.x, w.y);
    }
}

// Layer-1 GEMM (fused concat-out0) + count_deg in blocks >= gemmBlocks.
__global__ void __launch_bounds__(256) k_gemm1_count(
        const float4* __restrict__ u, const float4* __restrict__ it,
        const float* __restrict__ W, float4* __restrict__ out0,
        int nu4, int n, int gemmBlocks, const void* __restrict__ ei, int e) {
    __shared__ __half xs[128 * 72];
    __shared__ __half Ws[64 * 72];

    if (blockIdx.x >= (unsigned)gemmBlocks) {
        int bid = blockIdx.x - gemmBlocks;
        int i = (bid * 256 + threadIdx.x) * 2;
        if (i >= e) return;
        int c0, c1 = -1;
        if (i + 1 < e) {
            if (g_idx64) {
                longlong2 v = *(const longlong2*)((const long long*)ei + (size_t)e + i);
                c0 = (int)v.x; c1 = (int)v.y;
            } else {
                int2 v = *(const int2*)((const int*)ei + (size_t)e + i);
                c0 = v.x; c1 = v.y;
            }
        } else {
            c0 = g_idx64 ? (int)((const long long*)ei)[(size_t)e + i]
                         : ((const int*)ei)[(size_t)e + i];
        }
        if ((unsigned)c0 < (unsigned)n) atomicAdd(&g_deg[c0], 1);
        if (c1 >= 0 && (unsigned)c1 < (unsigned)n) atomicAdd(&g_deg[c1], 1);
        return;
    }

    int tid = threadIdx.x;
    int row0 = blockIdx.x * 128;
    int nr = n - row0; if (nr > 128) nr = 128;

    stage_W(W, Ws);
    {
        int tot4 = nr * 16, g0 = row0 * 16;
        for (int i = tid; i < tot4; i += 256) {
            int gi = g0 + i;
            float4 v = (gi < nu4) ? u[gi] : it[gi - nu4];
            out0[gi] = v;
            int row = i >> 4, k4 = i & 15;
            __half2* p = (__half2*)&xs[row * 72 + k4 * 4];
            p[0] = __floats2half2_rn(v.x, v.y);
            p[1] = __floats2half2_rn(v.z, v.w);
        }
        for (int i = nr * 16 + tid; i < 128 * 16; i += 256) {
            int row = i >> 4, k4 = i & 15;
            __half2* p = (__half2*)&xs[row * 72 + k4 * 4];
            p[0] = __half2half2(__float2half(0.0f));
            p[1] = __half2half2(__float2half(0.0f));
        }
    }
    __syncthreads();
    gemm_core(xs, Ws, row0, n);
}

// Layer-2 GEMM: reads out1 fp32 with relu.
__global__ void __launch_bounds__(256) k_gemm_l2(
        const float* __restrict__ x, const float* __restrict__ W, int n) {
    __shared__ __half xs[128 * 72];
    __shared__ __half Ws[64 * 72];
    int tid = threadIdx.x;
    int row0 = blockIdx.x * 128;
    int nr = n - row0; if (nr > 128) nr = 128;

    stage_W(W, Ws);
    {
        const float4* x4 = (const float4*)(x + (size_t)row0 * 64);
        int tot4 = nr * 16;
        for (int i = tid; i < tot4; i += 256) {
            float4 v = x4[i];
            v.x = fmaxf(v.x, 0.0f); v.y = fmaxf(v.y, 0.0f);
            v.z = fmaxf(v.z, 0.0f); v.w = fmaxf(v.w, 0.0f);
            int row = i >> 4, k4 = i & 15;
            __half2* p = (__half2*)&xs[row * 72 + k4 * 4];
            p[0] = __floats2half2_rn(v.x, v.y);
            p[1] = __floats2half2_rn(v.z, v.w);
        }
        for (int i = nr * 16 + tid; i < 128 * 16; i += 256) {
            int row = i >> 4, k4 = i & 15;
            __half2* p = (__half2*)&xs[row * 72 + k4 * 4];
            p[0] = __half2half2(__float2half(0.0f));
            p[1] = __half2half2(__float2half(0.0f));
        }
    }
    __syncthreads();
    gemm_core(xs, Ws, row0, n);
}

// ---------------- single-kernel scan (grid-resident spin sync) --------------
// All gridDim.x (<= 592) blocks are co-resident (__launch_bounds__(256,8)):
// each publishes its block sum (volatile) + bumps g_cnt; spins until all
// published; sums predecessors; writes offsets/pos/dinv.
__global__ void __launch_bounds__(256, 8) k_scan(int n) {
    __shared__ int wsum[8];
    __shared__ int s_bpre;
    int tid = threadIdx.x, lane = tid & 31, wid = tid >> 5;
    int i = blockIdx.x * 256 + tid;
    int d = (i < n) ? g_deg[i] : 0;
    int v = d;
    #pragma unroll
    for (int o = 1; o < 32; o <<= 1) {
        int t = __shfl_up_sync(~0u, v, o);
        if (lane >= o) v += t;
    }
    if (lane == 31) wsum[wid] = v;
    __syncthreads();
    if (wid == 0 && lane < 8) {
        int w = wsum[lane];
        #pragma unroll
        for (int o = 1; o < 8; o <<= 1) {
            int t = __shfl_up_sync(0xFFu, w, o);
            if (lane >= o) w += t;
        }
        wsum[lane] = w;
    }
    __syncthreads();
    int excl_blk = v - d + (wid > 0 ? wsum[wid - 1] : 0);
    int blk_total = wsum[7];

    if (tid == 0) {
        ((volatile int*)g_bsum)[blockIdx.x] = blk_total;
        __threadfence();
        atomicAdd(&g_cnt, 1);
    }
    // all threads spin until every block has published
    volatile int* cnt = &g_cnt;
    while (*cnt < (int)gridDim.x) { }
    __syncthreads();

    // block prefix = sum of predecessors' block sums (coalesced, volatile)
    {
        int part = 0;
        for (int bkt = tid; bkt < (int)blockIdx.x; bkt += 256)
            part += ((volatile int*)g_bsum)[bkt];
        #pragma unroll
        for (int o = 16; o > 0; o >>= 1) part += __shfl_down_sync(~0u, part, o);
        if (lane == 0) wsum[wid] = part;
        __syncthreads();
        if (tid == 0) {
            int s = 0;
            #pragma unroll
            for (int w = 0; w < 8; w++) s += wsum[w];
            s_bpre = s;
        }
        __syncthreads();
    }

    int excl = excl_blk + s_bpre;
    if (i < n) {
        g_off[i] = excl;
        g_pos[i] = excl;
        g_dinv[i] = rsqrtf((float)d + 1.0f);
        if (i == n - 1) g_off[n] = excl + d;
    }
}

// 4 edges per thread; scattered 8B store + int atomic per edge.
__global__ void k_build(const void* __restrict__ ei, int e, int n) {
    long long i = ((long long)(blockIdx.x * blockDim.x + threadIdx.x)) * 4;
    if (i >= e) return;
    int r[4], c[4], m = (e - i >= 4) ? 4 : (int)(e - i);
    if (m == 4) {
        if (g_idx64) {
            longlong2 ra = *(const longlong2*)((const long long*)ei + i);
            longlong2 rb = *(const longlong2*)((const long long*)ei + i + 2);
            longlong2 ca = *(const longlong2*)((const long long*)ei + (size_t)e + i);
            longlong2 cb = *(const longlong2*)((const long long*)ei + (size_t)e + i + 2);
            r[0] = (int)ra.x; r[1] = (int)ra.y; r[2] = (int)rb.x; r[3] = (int)rb.y;
            c[0] = (int)ca.x; c[1] = (int)ca.y; c[2] = (int)cb.x; c[3] = (int)cb.y;
        } else {
            int4 rv = *(const int4*)((const int*)ei + i);
            int4 cv = *(const int4*)((const int*)ei + (size_t)e + i);
            r[0] = rv.x; r[1] = rv.y; r[2] = rv.z; r[3] = rv.w;
            c[0] = cv.x; c[1] = cv.y; c[2] = cv.z; c[3] = cv.w;
        }
    } else {
        for (int t = 0; t < m; t++) {
            if (g_idx64) {
                r[t] = (int)((const long long*)ei)[i + t];
                c[t] = (int)((const long long*)ei)[(size_t)e + i + t];
            } else {
                r[t] = ((const int*)ei)[i + t];
                c[t] = ((const int*)ei)[(size_t)e + i + t];
            }
        }
    }
    #pragma unroll
    for (int t = 0; t < 4; t++) {
        if (t < m && (unsigned)r[t] < (unsigned)n && (unsigned)c[t] < (unsigned)n) {
            int p = atomicAdd(&g_pos[c[t]], 1);
            float cf = g_dinv[r[t]] * g_dinv[c[t]];
            g_edge[p] = ((unsigned long long)__float_as_uint(cf) << 32)
                        | (unsigned)r[t];
        }
    }
}

// Warp per node; lane owns dims {2*lane, 2*lane+1}. Uniform 8-batches:
// OOB lanes carry meta=0 (coef=+0, src=0) -> exact no-op, no serial tail.
__global__ void k_agg(const float* __restrict__ b, float* __restrict__ out, int n) {
    int node = (blockIdx.x * blockDim.x + threadIdx.x) >> 5;
    int lane = threadIdx.x & 31;
    if (node >= n) return;

    int p0 = g_off[node];
    int p1 = g_off[node + 1];
    float acc0 = 0.0f, acc1 = 0.0f;

    const __half2* xw2 = (const __half2*)g_xwh;

    int p = p0;
    while (p < p1) {
        int cnt = p1 - p; if (cnt > 32) cnt = 32;
        unsigned long long meta = 0;
        if (p + lane < p1) meta = __ldg(&g_edge[p + lane]);

        int nb = (cnt + 7) >> 3;
        for (int jb = 0; jb < nb; jb++) {
            __half2 h[8]; float cf[8];
            #pragma unroll
            for (int t = 0; t < 8; t++) {
                unsigned long long m = __shfl_sync(~0u, meta, jb * 8 + t);
                unsigned r = (unsigned)m;
                cf[t] = __uint_as_float((unsigned)(m >> 32));
                h[t] = __ldg(&xw2[r * 32u + (unsigned)lane]);
            }
            #pragma unroll
            for (int t = 0; t < 8; t++) {
                float2 f = __half22float2(h[t]);
                acc0 += f.x * cf[t];
                acc1 += f.y * cf[t];
            }
        }
        p += cnt;
    }

    float di = g_dinv[node];
    float d2 = di * di;
    float2 fs = __half22float2(xw2[(unsigned)node * 32u + (unsigned)lane]);
    float2 bb = ((const float2*)b)[lane];
    float2 o;
    o.x = acc0 + fs.x * d2 + bb.x;
    o.y = acc1 + fs.y * d2 + bb.y;
    ((float2*)out)[(unsigned)node * 32u + (unsigned)lane] = o;
}

extern "C" void kernel_launch(void* const* d_in, const int* in_sizes, int n_in,
                              void* d_out, int out_size) {
    const float* emb_users = (const float*)d_in[0];
    const float* emb_items = (const float*)d_in[1];
    const float* W1 = (const float*)d_in[2];
    const float* b1 = (const float*)d_in[3];
    const float* W2 = (const float*)d_in[4];
    const float* b2 = (const float*)d_in[5];
    const void*  ei = d_in[6];

    int NU = in_sizes[0] / D;
    int NI = in_sizes[1] / D;
    int N  = NU + NI;
    int E  = in_sizes[6] / 2;

    float* out0 = (float*)d_out;
    float* out1 = out0 + (size_t)N * D;
    float* out2 = out1 + (size_t)N * D;

    const int T = 256;
    int gN  = (N + T - 1) / T;                 // scan blocks (<= 592)
    int gE2 = (E / 2 + T - 1) / T;
    int gE4 = (E / 4 + T - 1) / T;
    int gW  = (int)(((long long)N * 32 + T - 1) / T);
    int gG  = (N + 127) / 128;

    k_init<<<gN + 1, T>>>((const unsigned long long*)ei, N, gN);
    k_gemm1_count<<<gG + gE2, T>>>((const float4*)emb_users,
                                   (const float4*)emb_items,
                                   W1, (float4*)out0, NU * 16, N, gG, ei, E);
    k_scan<<<gN, T>>>(N);
    k_build<<<gE4, T>>>(ei, E, N);
    k_agg<<<gW, T>>>(b1, out1, N);
    k_gemm_l2<<<gG, T>>>(out1, W2, N);
    k_agg<<<gW, T>>>(b2, out2, N);
}

// round 14
// speedup vs baseline: 2.8832x; 1.1739x over previous
#include <cuda_runtime.h>
#include <cuda_fp16.h>
#include <cuda_bf16.h>
#include <cstdint>

// GNN_26242250178821: 2-layer GCN forward, CSR-gather + fp16 feature rows.
// R14: symmetric-norm factored — GEMM epilogue pre-scales rows by dinv[row],
// CSR payload = 4B src only (build: 1 atomic + 1 int store, no dinv loads),
// build grid-fused with gemm1, agg does pure row sums * dinv[node].
//
// RULE: never pass a __device__ symbol as a kernel argument from host code —
// on GB300/ATS the host-shadow address is silently writable.

#define D 64
#define MAXN 150016
#define MAXE  3000064
#define MAXELEM (150016 * 64)
#define MAXB 1024

__device__ int    g_deg[MAXN];
__device__ int    g_off[MAXN + 1];
__device__ int    g_pos[MAXN];
__device__ float  g_dinv[MAXN];
__device__ int    g_bsum[MAXB];
__device__ int    g_cnt;
__device__ int    g_src[MAXE];     // CSR payload: src index only
__device__ __half g_xwh[MAXELEM];  // rows = xw * dinv[row], fp16, 128 B/row
__device__ int    g_idx64;

// blocks [0,gn): zero g_deg; block gn: probe + counter + sentinel row n.
__global__ void k_init(const unsigned long long* __restrict__ p, int n, int gn) {
    if (blockIdx.x == (unsigned)gn) {
        __shared__ int any;
        if (threadIdx.x == 0) { any = 0; g_cnt = 0; }
        __syncthreads();
        for (int i = threadIdx.x; i < 256; i += blockDim.x)
            if ((p[i] >> 32) != 0ull) any = 1;
        if (threadIdx.x < 32)   // zero sentinel row n of g_xwh (64 halves)
            ((uint32_t*)g_xwh)[(size_t)n * 32 + threadIdx.x] = 0u;
        __syncthreads();
        if (threadIdx.x == 0) g_idx64 = any ? 0 : 1;
        return;
    }
    int i = blockIdx.x * blockDim.x + threadIdx.x;
    if (i < n) g_deg[i] = 0;
}

// 2 edges per thread degree count.
__global__ void k_count(const void* __restrict__ ei, int e, int n) {
    int i = (blockIdx.x * blockDim.x + threadIdx.x) * 2;
    if (i >= e) return;
    int c0, c1 = -1;
    if (i + 1 < e) {
        if (g_idx64) {
            longlong2 v = *(const longlong2*)((const long long*)ei + (size_t)e + i);
            c0 = (int)v.x; c1 = (int)v.y;
        } else {
            int2 v = *(const int2*)((const int*)ei + (size_t)e + i);
            c0 = v.x; c1 = v.y;
        }
    } else {
        c0 = g_idx64 ? (int)((const long long*)ei)[(size_t)e + i]
                     : ((const int*)ei)[(size_t)e + i];
    }
    if ((unsigned)c0 < (unsigned)n) atomicAdd(&g_deg[c0], 1);
    if (c1 >= 0 && (unsigned)c1 < (unsigned)n) atomicAdd(&g_deg[c1], 1);
}

// Single-kernel scan with grid-resident spin sync (blocks <= 592, occ 8/SM).
__global__ void __launch_bounds__(256, 8) k_scan(int n) {
    __shared__ int wsum[8];
    __shared__ int s_bpre;
    int tid = threadIdx.x, lane = tid & 31, wid = tid >> 5;
    int i = blockIdx.x * 256 + tid;
    int d = (i < n) ? g_deg[i] : 0;
    int v = d;
    #pragma unroll
    for (int o = 1; o < 32; o <<= 1) {
        int t = __shfl_up_sync(~0u, v, o);
        if (lane >= o) v += t;
    }
    if (lane == 31) wsum[wid] = v;
    __syncthreads();
    if (wid == 0 && lane < 8) {
        int w = wsum[lane];
        #pragma unroll
        for (int o = 1; o < 8; o <<= 1) {
            int t = __shfl_up_sync(0xFFu, w, o);
            if (lane >= o) w += t;
        }
        wsum[lane] = w;
    }
    __syncthreads();
    int excl_blk = v - d + (wid > 0 ? wsum[wid - 1] : 0);
    int blk_total = wsum[7];

    if (tid == 0) {
        ((volatile int*)g_bsum)[blockIdx.x] = blk_total;
        __threadfence();
        atomicAdd(&g_cnt, 1);
    }
    volatile int* cnt = &g_cnt;
    while (*cnt < (int)gridDim.x) { }
    __syncthreads();

    {
        int part = 0;
        for (int bkt = tid; bkt < (int)blockIdx.x; bkt += 256)
            part += ((volatile int*)g_bsum)[bkt];
        #pragma unroll
        for (int o = 16; o > 0; o >>= 1) part += __shfl_down_sync(~0u, part, o);
        if (lane == 0) wsum[wid] = part;
        __syncthreads();
        if (tid == 0) {
            int s = 0;
            #pragma unroll
            for (int w = 0; w < 8; w++) s += wsum[w];
            s_bpre = s;
        }
        __syncthreads();
    }

    int excl = excl_blk + s_bpre;
    if (i < n) {
        g_off[i] = excl;
        g_pos[i] = excl;
        g_dinv[i] = rsqrtf((float)d + 1.0f);
        if (i == n - 1) g_off[n] = excl + d;
    }
}

// ---------------- tensor-core GEMM core (rows scaled by dinv) --------------

__device__ __forceinline__ void ldsm_x4(uint32_t& r0, uint32_t& r1,
                                        uint32_t& r2, uint32_t& r3, uint32_t a) {
    asm volatile("ldmatrix.sync.aligned.m8n8.x4.shared.b16 {%0,%1,%2,%3},[%4];"
                 : "=r"(r0), "=r"(r1), "=r"(r2), "=r"(r3) : "r"(a));
}
__device__ __forceinline__ void ldsm_x4t(uint32_t& r0, uint32_t& r1,
                                         uint32_t& r2, uint32_t& r3, uint32_t a) {
    asm volatile("ldmatrix.sync.aligned.m8n8.x4.trans.shared.b16 {%0,%1,%2,%3},[%4];"
                 : "=r"(r0), "=r"(r1), "=r"(r2), "=r"(r3) : "r"(a));
}
__device__ __forceinline__ void mma16816(float* d, uint32_t a0, uint32_t a1,
                                         uint32_t a2, uint32_t a3,
                                         uint32_t b0, uint32_t b1) {
    asm volatile(
        "mma.sync.aligned.m16n8k16.row.col.f32.f16.f16.f32 "
        "{%0,%1,%2,%3},{%4,%5,%6,%7},{%8,%9},{%0,%1,%2,%3};"
        : "+f"(d[0]), "+f"(d[1]), "+f"(d[2]), "+f"(d[3])
        : "r"(a0), "r"(a1), "r"(a2), "r"(a3), "r"(b0), "r"(b1));
}

// Computes 128x64 tile, stores g_xwh[row] = (x@W)[row] * dinv[row].
__device__ __forceinline__ void gemm_core(const __half* xs, const __half* Ws,
                                          int row0, int n) {
    int tid = threadIdx.x;
    int warp = tid >> 5, lane = tid & 31;
    int warpRow = warp * 16;

    float d[8][4];
    #pragma unroll
    for (int t = 0; t < 8; t++)
        #pragma unroll
        for (int q = 0; q < 4; q++) d[t][q] = 0.0f;

    int rin = lane & 15, half_sel = lane >> 4;
    #pragma unroll
    for (int ks = 0; ks < 4; ks++) {
        uint32_t a0, a1, a2, a3;
        uint32_t aaddr = (uint32_t)__cvta_generic_to_shared(
            &xs[(warpRow + rin) * 72 + ks * 16 + half_sel * 8]);
        ldsm_x4(a0, a1, a2, a3, aaddr);
        #pragma unroll
        for (int jp = 0; jp < 4; jp++) {
            uint32_t b0, b1, b2, b3;
            uint32_t baddr = (uint32_t)__cvta_generic_to_shared(
                &Ws[(ks * 16 + rin) * 72 + (jp * 2 + half_sel) * 8]);
            ldsm_x4t(b0, b1, b2, b3, baddr);
            mma16816(d[jp * 2],     a0, a1, a2, a3, b0, b1);
            mma16816(d[jp * 2 + 1], a0, a1, a2, a3, b2, b3);
        }
    }

    int group = lane >> 2, tig = lane & 3;
    int row_lo = row0 + warpRow + group;
    int row_hi = row_lo + 8;
    float dv_lo = (row_lo < n) ? g_dinv[row_lo] : 0.0f;
    float dv_hi = (row_hi < n) ? g_dinv[row_hi] : 0.0f;
    __half2* xwh2 = (__half2*)g_xwh;
    #pragma unroll
    for (int t = 0; t < 8; t++) {
        int cidx = t * 4 + tig;
        if (row_lo < n)
            xwh2[(size_t)row_lo * 32 + cidx] =
                __floats2half2_rn(d[t][0] * dv_lo, d[t][1] * dv_lo);
        if (row_hi < n)
            xwh2[(size_t)row_hi * 32 + cidx] =
                __floats2half2_rn(d[t][2] * dv_hi, d[t][3] * dv_hi);
    }
}

__device__ __forceinline__ void stage_W(const float* __restrict__ W, __half* Ws) {
    const float2* W2 = (const float2*)W;
    for (int i = threadIdx.x; i < 2048; i += 256) {
        int k = i >> 5, np = i & 31;
        float2 w = W2[i];
        *(__half2*)&Ws[k * 72 + np * 2] = __floats2half2_rn(w.x, w.y);
    }
}

// Layer-1 GEMM (fused concat-out0, dinv-scaled) grid-fused with CSR build.
// blocks [0, gemmBlocks): GEMM; blocks >= gemmBlocks: build (4 edges/thread).
__global__ void __launch_bounds__(256) k_gemm1_build(
        const float4* __restrict__ u, const float4* __restrict__ it,
        const float* __restrict__ W, float4* __restrict__ out0,
        int nu4, int n, int gemmBlocks, const void* __restrict__ ei, int e) {
    __shared__ __half xs[128 * 72];
    __shared__ __half Ws[64 * 72];

    if (blockIdx.x >= (unsigned)gemmBlocks) {
        int bid = blockIdx.x - gemmBlocks;
        long long i = ((long long)bid * 256 + threadIdx.x) * 4;
        if (i >= e) return;
        int r[4], c[4], m = (e - i >= 4) ? 4 : (int)(e - i);
        if (m == 4) {
            if (g_idx64) {
                longlong2 ra = *(const longlong2*)((const long long*)ei + i);
                longlong2 rb = *(const longlong2*)((const long long*)ei + i + 2);
                longlong2 ca = *(const longlong2*)((const long long*)ei + (size_t)e + i);
                longlong2 cb = *(const longlong2*)((const long long*)ei + (size_t)e + i + 2);
                r[0] = (int)ra.x; r[1] = (int)ra.y; r[2] = (int)rb.x; r[3] = (int)rb.y;
                c[0] = (int)ca.x; c[1] = (int)ca.y; c[2] = (int)cb.x; c[3] = (int)cb.y;
            } else {
                int4 rv = *(const int4*)((const int*)ei + i);
                int4 cv = *(const int4*)((const int*)ei + (size_t)e + i);
                r[0] = rv.x; r[1] = rv.y; r[2] = rv.z; r[3] = rv.w;
                c[0] = cv.x; c[1] = cv.y; c[2] = cv.z; c[3] = cv.w;
            }
        } else {
            for (int t = 0; t < m; t++) {
                if (g_idx64) {
                    r[t] = (int)((const long long*)ei)[i + t];
                    c[t] = (int)((const long long*)ei)[(size_t)e + i + t];
                } else {
                    r[t] = ((const int*)ei)[i + t];
                    c[t] = ((const int*)ei)[(size_t)e + i + t];
                }
            }
        }
        #pragma unroll
        for (int t = 0; t < 4; t++) {
            if (t < m && (unsigned)r[t] < (unsigned)n && (unsigned)c[t] < (unsigned)n) {
                int p = atomicAdd(&g_pos[c[t]], 1);
                g_src[p] = r[t];
            }
        }
        return;
    }

    int tid = threadIdx.x;
    int row0 = blockIdx.x * 128;
    int nr = n - row0; if (nr > 128) nr = 128;

    stage_W(W, Ws);
    {
        int tot4 = nr * 16, g0 = row0 * 16;
        for (int i = tid; i < tot4; i += 256) {
            int gi = g0 + i;
            float4 v = (gi < nu4) ? u[gi] : it[gi - nu4];
            out0[gi] = v;
            int row = i >> 4, k4 = i & 15;
            __half2* p = (__half2*)&xs[row * 72 + k4 * 4];
            p[0] = __floats2half2_rn(v.x, v.y);
            p[1] = __floats2half2_rn(v.z, v.w);
        }
        for (int i = nr * 16 + tid; i < 128 * 16; i += 256) {
            int row = i >> 4, k4 = i & 15;
            __half2* p = (__half2*)&xs[row * 72 + k4 * 4];
            p[0] = __half2half2(__float2half(0.0f));
            p[1] = __half2half2(__float2half(0.0f));
        }
    }
    __syncthreads();
    gemm_core(xs, Ws, row0, n);
}

// Layer-2 GEMM: reads out1 fp32 with relu, stores dinv-scaled rows.
__global__ void __launch_bounds__(256) k_gemm_l2(
        const float* __restrict__ x, const float* __restrict__ W, int n) {
    __shared__ __half xs[128 * 72];
    __shared__ __half Ws[64 * 72];
    int tid = threadIdx.x;
    int row0 = blockIdx.x * 128;
    int nr = n - row0; if (nr > 128) nr = 128;

    stage_W(W, Ws);
    {
        const float4* x4 = (const float4*)(x + (size_t)row0 * 64);
        int tot4 = nr * 16;
        for (int i = tid; i < tot4; i += 256) {
            float4 v = x4[i];
            v.x = fmaxf(v.x, 0.0f); v.y = fmaxf(v.y, 0.0f);
            v.z = fmaxf(v.z, 0.0f); v.w = fmaxf(v.w, 0.0f);
            int row = i >> 4, k4 = i & 15;
            __half2* p = (__half2*)&xs[row * 72 + k4 * 4];
            p[0] = __floats2half2_rn(v.x, v.y);
            p[1] = __floats2half2_rn(v.z, v.w);
        }
        for (int i = nr * 16 + tid; i < 128 * 16; i += 256) {
            int row = i >> 4, k4 = i & 15;
            __half2* p = (__half2*)&xs[row * 72 + k4 * 4];
            p[0] = __half2half2(__float2half(0.0f));
            p[1] = __half2half2(__float2half(0.0f));
        }
    }
    __syncthreads();
    gemm_core(xs, Ws, row0, n);
}

// Warp per node; lane owns dims {2*lane, 2*lane+1}. Rows pre-scaled by
// dinv[src], so agg is pure adds; OOB lanes use sentinel zero row n.
// out[i] = dinv[i] * (sum + xws[i]) + b   (xws = xw*dinv)
__global__ void k_agg(const float* __restrict__ b, float* __restrict__ out, int n) {
    int node = (blockIdx.x * blockDim.x + threadIdx.x) >> 5;
    int lane = threadIdx.x & 31;
    if (node >= n) return;

    int p0 = g_off[node];
    int p1 = g_off[node + 1];
    float acc0 = 0.0f, acc1 = 0.0f;

    const __half2* xw2 = (const __half2*)g_xwh;

    int p = p0;
    while (p < p1) {
        int cnt = p1 - p; if (cnt > 32) cnt = 32;
        int meta = n;                       // sentinel zero row
        if (p + lane < p1) meta = __ldg(&g_src[p + lane]);

        int nb = (cnt + 7) >> 3;
        for (int jb = 0; jb < nb; jb++) {
            __half2 h[8];
            #pragma unroll
            for (int t = 0; t < 8; t++) {
                unsigned r = (unsigned)__shfl_sync(~0u, meta, jb * 8 + t);
                h[t] = __ldg(&xw2[r * 32u + (unsigned)lane]);
            }
            #pragma unroll
            for (int t = 0; t < 8; t++) {
                float2 f = __half22float2(h[t]);
                acc0 += f.x;
                acc1 += f.y;
            }
        }
        p += cnt;
    }

    float di = g_dinv[node];
    float2 fs = __half22float2(xw2[(unsigned)node * 32u + (unsigned)lane]);
    float2 bb = ((const float2*)b)[lane];
    float2 o;
    o.x = fmaf(di, acc0 + fs.x, bb.x);
    o.y = fmaf(di, acc1 + fs.y, bb.y);
    ((float2*)out)[(unsigned)node * 32u + (unsigned)lane] = o;
}

extern "C" void kernel_launch(void* const* d_in, const int* in_sizes, int n_in,
                              void* d_out, int out_size) {
    const float* emb_users = (const float*)d_in[0];
    const float* emb_items = (const float*)d_in[1];
    const float* W1 = (const float*)d_in[2];
    const float* b1 = (const float*)d_in[3];
    const float* W2 = (const float*)d_in[4];
    const float* b2 = (const float*)d_in[5];
    const void*  ei = d_in[6];

    int NU = in_sizes[0] / D;
    int NI = in_sizes[1] / D;
    int N  = NU + NI;
    int E  = in_sizes[6] / 2;

    float* out0 = (float*)d_out;
    float* out1 = out0 + (size_t)N * D;
    float* out2 = out1 + (size_t)N * D;

    const int T = 256;
    int gN  = (N + T - 1) / T;
    int gE2 = (E / 2 + T - 1) / T;
    int gE4 = (E / 4 + T - 1) / T;
    int gW  = (int)(((long long)N * 32 + T - 1) / T);
    int gG  = (N + 127) / 128;

    k_init<<<gN + 1, T>>>((const unsigned long long*)ei, N, gN);
    k_count<<<gE2, T>>>(ei, E, N);
    k_scan<<<gN, T>>>(N);
    k_gemm1_build<<<gG + gE4, T>>>((const float4*)emb_users,
                                   (const float4*)emb_items,
                                   W1, (float4*)out0, NU * 16, N, gG, ei, E);
    k_agg<<<gW, T>>>(b1, out1, N);
    k_gemm_l2<<<gG, T>>>(out1, W2, N);
    k_agg<<<gW, T>>>(b2, out2, N);
}